// round 3
// baseline (speedup 1.0000x reference)
#include <cuda_runtime.h>
#include <cuda_bf16.h>
#include <cstdint>

// ===================== problem dims =====================
#define TOK    8192
#define HID    4096
#define KACT   3302
#define KPAD   3328      // 52 * 64
#define WFULL  11008
#define NCH1   64        // 4096 / 64
#define NCH2   52        // 3328 / 64

// ===================== device scratch (static, no allocs) =====================
__device__ __nv_bfloat16 g_xh[(size_t)TOK * HID];
__device__ __nv_bfloat16 g_xl[(size_t)TOK * HID];
__device__ __nv_bfloat16 g_wgh[(size_t)KPAD * HID];
__device__ __nv_bfloat16 g_wgl[(size_t)KPAD * HID];
__device__ __nv_bfloat16 g_wuh[(size_t)KPAD * HID];
__device__ __nv_bfloat16 g_wul[(size_t)KPAD * HID];
__device__ __nv_bfloat16 g_wdh[(size_t)HID * KPAD];
__device__ __nv_bfloat16 g_wdl[(size_t)HID * KPAD];
__device__ __nv_bfloat16 g_hh[(size_t)TOK * KPAD];
__device__ __nv_bfloat16 g_hl[(size_t)TOK * KPAD];

// ===================== low-level helpers =====================
__device__ __forceinline__ uint32_t smem_u32(const void* p) {
    uint32_t a;
    asm("{ .reg .u64 t; cvta.to.shared.u64 t, %1; cvt.u32.u64 %0, t; }" : "=r"(a) : "l"(p));
    return a;
}
__device__ __forceinline__ uint32_t swz(uint32_t off) {   // SW128: bits[6:4] ^= bits[9:7]
    return off ^ ((off >> 3) & 0x70);
}
#define CP_COMMIT() asm volatile("cp.async.commit_group;" ::: "memory")
#define CP_WAIT2()  asm volatile("cp.async.wait_group 2;" ::: "memory")

__device__ __forceinline__ void cp16(uint32_t d, const void* s) {
    asm volatile("cp.async.cg.shared.global [%0], [%1], 16;" :: "r"(d), "l"(s));
}

// Load ROWS x 64 bf16 K-major tile into SW128 smem with cp.async (256 threads)
template<int ROWS>
__device__ __forceinline__ void cp_tile(uint32_t dbase, const __nv_bfloat16* __restrict__ src, int ld) {
#pragma unroll
    for (int it = 0; it < (ROWS * 8) / 256; ++it) {
        int i = threadIdx.x + it * 256;
        int row = i >> 3, c = i & 7;
        uint32_t off = (uint32_t)(row * 128 + c * 16);
        cp16(dbase + swz(off), src + (size_t)row * ld + c * 8);
    }
}

__device__ __forceinline__ void ldsm_x4(uint32_t* r, uint32_t addr) {
    asm volatile("ldmatrix.sync.aligned.m8n8.x4.shared.b16 {%0,%1,%2,%3}, [%4];"
                 : "=r"(r[0]), "=r"(r[1]), "=r"(r[2]), "=r"(r[3]) : "r"(addr));
}

__device__ __forceinline__ void mma_bf16(float* c, const uint32_t* a, uint32_t b0, uint32_t b1) {
    asm volatile("mma.sync.aligned.m16n8k16.row.col.f32.bf16.bf16.f32 "
                 "{%0,%1,%2,%3}, {%4,%5,%6,%7}, {%8,%9}, {%0,%1,%2,%3};"
                 : "+f"(c[0]), "+f"(c[1]), "+f"(c[2]), "+f"(c[3])
                 : "r"(a[0]), "r"(a[1]), "r"(a[2]), "r"(a[3]), "r"(b0), "r"(b1));
}

// ===================== split kernels =====================
__device__ __forceinline__ void split4_store(const float* v, __nv_bfloat16* ph, __nv_bfloat16* pl) {
    __nv_bfloat16 h[4], l[4];
#pragma unroll
    for (int j = 0; j < 4; ++j) {
        h[j] = __float2bfloat16(v[j]);
        l[j] = __float2bfloat16(v[j] - __bfloat162float(h[j]));
    }
    *reinterpret_cast<uint2*>(ph) = *reinterpret_cast<const uint2*>(h);
    *reinterpret_cast<uint2*>(pl) = *reinterpret_cast<const uint2*>(l);
}

__global__ void __launch_bounds__(256) split_x_kernel(const float* __restrict__ x) {
    int idx4 = (blockIdx.x * 256 + threadIdx.x) * 4;
    float4 f = *reinterpret_cast<const float4*>(x + idx4);
    float v[4] = {f.x, f.y, f.z, f.w};
    split4_store(v, g_xh + idx4, g_xl + idx4);
}

__global__ void __launch_bounds__(256) split_gu_kernel(const float* __restrict__ Wg,
                                                       const float* __restrict__ Wu,
                                                       const int* __restrict__ aidx) {
    int idx4 = (blockIdx.x * 256 + threadIdx.x) * 4;   // < KPAD*HID
    int r = idx4 >> 12;
    int c = idx4 & 4095;
    float vg[4] = {0.f, 0.f, 0.f, 0.f};
    float vu[4] = {0.f, 0.f, 0.f, 0.f};
    if (r < KACT) {
        int a = aidx[r];
        float4 fg = *reinterpret_cast<const float4*>(Wg + (size_t)a * HID + c);
        float4 fu = *reinterpret_cast<const float4*>(Wu + (size_t)a * HID + c);
        vg[0] = fg.x; vg[1] = fg.y; vg[2] = fg.z; vg[3] = fg.w;
        vu[0] = fu.x; vu[1] = fu.y; vu[2] = fu.z; vu[3] = fu.w;
    }
    split4_store(vg, g_wgh + idx4, g_wgl + idx4);
    split4_store(vu, g_wuh + idx4, g_wul + idx4);
}

__global__ void __launch_bounds__(256) split_wd_kernel(const float* __restrict__ Wd,
                                                       const int* __restrict__ aidx) {
    int idx4 = (blockIdx.x * 256 + threadIdx.x) * 4;   // < HID*KPAD
    int hh = idx4 / KPAD;
    int r  = idx4 - hh * KPAD;
    float v[4];
#pragma unroll
    for (int j = 0; j < 4; ++j) {
        int k = r + j;
        v[j] = (k < KACT) ? Wd[(size_t)hh * WFULL + aidx[k]] : 0.f;
    }
    split4_store(v, g_wdh + idx4, g_wdl + idx4);
}

// ===================== GEMM1: h = silu(x Wg^T) * (x Wu^T) =====================
// CTA tile: M=128, N=64 (both g and u). 8 warps: wm in [0,4) x 32 rows, wn in [0,2) x 32 cols.
// K chunks of 64, 3-stage cp.async pipeline.
#define STG1   65536
#define SMEM_REQ (3 * 65536 + 1024)

__global__ void __launch_bounds__(256, 1) gemm1_kernel() {
    extern __shared__ char smem_raw[];
    char* smem = (char*)(((uintptr_t)smem_raw + 1023) & ~(uintptr_t)1023);
    uint32_t sb = smem_u32(smem);
    const int tid = threadIdx.x, l = tid & 31, wid = tid >> 5;
    const int wm = wid & 3, wn = wid >> 2;
    const int bM = blockIdx.x, bN = blockIdx.y;

    const __nv_bfloat16* Ah = g_xh  + (size_t)bM * 128 * HID;
    const __nv_bfloat16* Al = g_xl  + (size_t)bM * 128 * HID;
    const __nv_bfloat16* Gh = g_wgh + (size_t)bN * 64 * HID;
    const __nv_bfloat16* Gl = g_wgl + (size_t)bN * 64 * HID;
    const __nv_bfloat16* Uh = g_wuh + (size_t)bN * 64 * HID;
    const __nv_bfloat16* Ul = g_wul + (size_t)bN * 64 * HID;

    float acc_g[2][4][4] = {};
    float acc_u[2][4][4] = {};

    auto load_stage = [&](int ch, int s) {
        uint32_t base = sb + s * STG1;
        cp_tile<128>(base +     0, Ah + ch * 64, HID);
        cp_tile<128>(base + 16384, Al + ch * 64, HID);
        cp_tile<64> (base + 32768, Gh + ch * 64, HID);
        cp_tile<64> (base + 40960, Gl + ch * 64, HID);
        cp_tile<64> (base + 49152, Uh + ch * 64, HID);
        cp_tile<64> (base + 57344, Ul + ch * 64, HID);
    };

    load_stage(0, 0); CP_COMMIT();
    load_stage(1, 1); CP_COMMIT();

    for (int ch = 0; ch < NCH1; ++ch) {
        if (ch + 2 < NCH1) load_stage(ch + 2, (ch + 2) % 3);
        CP_COMMIT();
        CP_WAIT2();
        __syncthreads();
        uint32_t base = sb + (ch % 3) * STG1;

#pragma unroll
        for (int kk = 0; kk < 4; ++kk) {
            uint32_t ah[2][4], alr[2][4];
#pragma unroll
            for (int mi = 0; mi < 2; ++mi) {
                uint32_t off = (uint32_t)((wm * 32 + mi * 16 + (l & 15)) * 128 + (kk * 2 + (l >> 4)) * 16);
                ldsm_x4(ah[mi],  base +     0 + swz(off));
                ldsm_x4(alr[mi], base + 16384 + swz(off));
            }
            uint32_t bgh[2][4], bgl[2][4], buh[2][4], bul[2][4];
#pragma unroll
            for (int ni = 0; ni < 2; ++ni) {
                uint32_t off = (uint32_t)((wn * 32 + ni * 16 + (l & 15)) * 128 + (kk * 2 + (l >> 4)) * 16);
                ldsm_x4(bgh[ni], base + 32768 + swz(off));
                ldsm_x4(bgl[ni], base + 40960 + swz(off));
                ldsm_x4(buh[ni], base + 49152 + swz(off));
                ldsm_x4(bul[ni], base + 57344 + swz(off));
            }
#pragma unroll
            for (int mi = 0; mi < 2; ++mi)
#pragma unroll
                for (int ni = 0; ni < 2; ++ni)
#pragma unroll
                    for (int h = 0; h < 2; ++h) {
                        int nj = ni * 2 + h;
                        mma_bf16(acc_g[mi][nj], ah[mi],  bgh[ni][h], bgh[ni][2 + h]);
                        mma_bf16(acc_g[mi][nj], alr[mi], bgh[ni][h], bgh[ni][2 + h]);
                        mma_bf16(acc_g[mi][nj], ah[mi],  bgl[ni][h], bgl[ni][2 + h]);
                        mma_bf16(acc_u[mi][nj], ah[mi],  buh[ni][h], buh[ni][2 + h]);
                        mma_bf16(acc_u[mi][nj], alr[mi], buh[ni][h], buh[ni][2 + h]);
                        mma_bf16(acc_u[mi][nj], ah[mi],  bul[ni][h], bul[ni][2 + h]);
                    }
        }
        __syncthreads();
    }

    // Epilogue: h = silu(g)*u, hi/lo split, direct gmem stores.
#pragma unroll
    for (int mi = 0; mi < 2; ++mi)
#pragma unroll
        for (int nj = 0; nj < 4; ++nj) {
            int r = bM * 128 + wm * 32 + mi * 16 + (l >> 2);
            int c = bN * 64 + wn * 32 + nj * 8 + (l & 3) * 2;
#pragma unroll
            for (int half = 0; half < 2; ++half) {
                float g0 = acc_g[mi][nj][half * 2 + 0], g1 = acc_g[mi][nj][half * 2 + 1];
                float u0 = acc_u[mi][nj][half * 2 + 0], u1 = acc_u[mi][nj][half * 2 + 1];
                float h0 = u0 * g0 / (1.f + __expf(-g0));
                float h1 = u1 * g1 / (1.f + __expf(-g1));
                __nv_bfloat16 h0h = __float2bfloat16(h0);
                __nv_bfloat16 h1h = __float2bfloat16(h1);
                __nv_bfloat16 h0l = __float2bfloat16(h0 - __bfloat162float(h0h));
                __nv_bfloat16 h1l = __float2bfloat16(h1 - __bfloat162float(h1h));
                size_t off = (size_t)(r + half * 8) * KPAD + c;
                __nv_bfloat162 ph; ph.x = h0h; ph.y = h1h;
                __nv_bfloat162 pl; pl.x = h0l; pl.y = h1l;
                *reinterpret_cast<__nv_bfloat162*>(g_hh + off) = ph;
                *reinterpret_cast<__nv_bfloat162*>(g_hl + off) = pl;
            }
        }
}

// ===================== GEMM2: out = h Wd^T =====================
// CTA tile: M=128, N=128. 8 warps: wm in [0,4) x 32 rows, wn in [0,2) x 64 cols.
__global__ void __launch_bounds__(256, 1) gemm2_kernel(float* __restrict__ out) {
    extern __shared__ char smem_raw[];
    char* smem = (char*)(((uintptr_t)smem_raw + 1023) & ~(uintptr_t)1023);
    uint32_t sb = smem_u32(smem);
    const int tid = threadIdx.x, l = tid & 31, wid = tid >> 5;
    const int wm = wid & 3, wn = wid >> 2;
    const int bM = blockIdx.x, bN = blockIdx.y;

    const __nv_bfloat16* Ah = g_hh  + (size_t)bM * 128 * KPAD;
    const __nv_bfloat16* Al = g_hl  + (size_t)bM * 128 * KPAD;
    const __nv_bfloat16* Bh = g_wdh + (size_t)bN * 128 * KPAD;
    const __nv_bfloat16* Bl = g_wdl + (size_t)bN * 128 * KPAD;

    float acc[2][8][4] = {};

    auto load_stage = [&](int ch, int s) {
        uint32_t base = sb + s * STG1;
        cp_tile<128>(base +     0, Ah + ch * 64, KPAD);
        cp_tile<128>(base + 16384, Al + ch * 64, KPAD);
        cp_tile<128>(base + 32768, Bh + ch * 64, KPAD);
        cp_tile<128>(base + 49152, Bl + ch * 64, KPAD);
    };

    load_stage(0, 0); CP_COMMIT();
    load_stage(1, 1); CP_COMMIT();

    for (int ch = 0; ch < NCH2; ++ch) {
        if (ch + 2 < NCH2) load_stage(ch + 2, (ch + 2) % 3);
        CP_COMMIT();
        CP_WAIT2();
        __syncthreads();
        uint32_t base = sb + (ch % 3) * STG1;

#pragma unroll
        for (int kk = 0; kk < 4; ++kk) {
            uint32_t ah[2][4], alr[2][4];
#pragma unroll
            for (int mi = 0; mi < 2; ++mi) {
                uint32_t off = (uint32_t)((wm * 32 + mi * 16 + (l & 15)) * 128 + (kk * 2 + (l >> 4)) * 16);
                ldsm_x4(ah[mi],  base +     0 + swz(off));
                ldsm_x4(alr[mi], base + 16384 + swz(off));
            }
            uint32_t bh[4][4], bl[4][4];
#pragma unroll
            for (int g4 = 0; g4 < 4; ++g4) {
                uint32_t off = (uint32_t)((wn * 64 + g4 * 16 + (l & 15)) * 128 + (kk * 2 + (l >> 4)) * 16);
                ldsm_x4(bh[g4], base + 32768 + swz(off));
                ldsm_x4(bl[g4], base + 49152 + swz(off));
            }
#pragma unroll
            for (int mi = 0; mi < 2; ++mi)
#pragma unroll
                for (int g4 = 0; g4 < 4; ++g4)
#pragma unroll
                    for (int h = 0; h < 2; ++h) {
                        int nj = g4 * 2 + h;
                        mma_bf16(acc[mi][nj], ah[mi],  bh[g4][h], bh[g4][2 + h]);
                        mma_bf16(acc[mi][nj], alr[mi], bh[g4][h], bh[g4][2 + h]);
                        mma_bf16(acc[mi][nj], ah[mi],  bl[g4][h], bl[g4][2 + h]);
                    }
        }
        __syncthreads();
    }

    // Epilogue: fp32 direct stores (8B per frag-row).
#pragma unroll
    for (int mi = 0; mi < 2; ++mi)
#pragma unroll
        for (int nj = 0; nj < 8; ++nj) {
            int r = bM * 128 + wm * 32 + mi * 16 + (l >> 2);
            int c = bN * 128 + wn * 64 + nj * 8 + (l & 3) * 2;
            float2 v0; v0.x = acc[mi][nj][0]; v0.y = acc[mi][nj][1];
            float2 v1; v1.x = acc[mi][nj][2]; v1.y = acc[mi][nj][3];
            *reinterpret_cast<float2*>(out + (size_t)r * HID + c) = v0;
            *reinterpret_cast<float2*>(out + (size_t)(r + 8) * HID + c) = v1;
        }
}

// ===================== launch =====================
extern "C" void kernel_launch(void* const* d_in, const int* in_sizes, int n_in,
                              void* d_out, int out_size) {
    const float* x  = (const float*)d_in[0];
    const float* Wg = (const float*)d_in[1];
    const float* Wu = (const float*)d_in[2];
    const float* Wd = (const float*)d_in[3];
    const int* aidx = (const int*)d_in[4];
    float* out = (float*)d_out;

    cudaFuncSetAttribute(gemm1_kernel, cudaFuncAttributeMaxDynamicSharedMemorySize, SMEM_REQ);
    cudaFuncSetAttribute(gemm2_kernel, cudaFuncAttributeMaxDynamicSharedMemorySize, SMEM_REQ);

    split_x_kernel<<<(TOK * (size_t)HID) / 1024, 256>>>(x);
    split_gu_kernel<<<((size_t)KPAD * HID) / 1024, 256>>>(Wg, Wu, aidx);
    split_wd_kernel<<<((size_t)HID * KPAD) / 1024, 256>>>(Wd, aidx);
    gemm1_kernel<<<dim3(64, 52), 256, SMEM_REQ>>>();
    gemm2_kernel<<<dim3(64, 32), 256, SMEM_REQ>>>(out);
}

// round 4
// speedup vs baseline: 1.5705x; 1.5705x over previous
#include <cuda_runtime.h>
#include <cuda_fp16.h>
#include <cstdint>

// ===================== problem dims =====================
#define TOK    8192
#define HID    4096
#define KACT   3302
#define KPAD   3328      // 52 * 64
#define WFULL  11008
#define NCH1   64        // 4096 / 64
#define NCH2   52        // 3328 / 64

// ===================== device scratch (static, no allocs) =====================
__device__ __half g_xh[(size_t)TOK * HID];
__device__ __half g_xl[(size_t)TOK * HID];
__device__ __half g_wg[(size_t)KPAD * HID];
__device__ __half g_wu[(size_t)KPAD * HID];
__device__ __half g_wd[(size_t)HID * KPAD];
__device__ __half g_hh[(size_t)TOK * KPAD];
__device__ __half g_hl[(size_t)TOK * KPAD];

// ===================== low-level helpers =====================
__device__ __forceinline__ uint32_t smem_u32(const void* p) {
    uint32_t a;
    asm("{ .reg .u64 t; cvta.to.shared.u64 t, %1; cvt.u32.u64 %0, t; }" : "=r"(a) : "l"(p));
    return a;
}
__device__ __forceinline__ uint32_t swz(uint32_t off) {   // SW128: bits[6:4] ^= bits[9:7]
    return off ^ ((off >> 3) & 0x70);
}
#define CP_COMMIT() asm volatile("cp.async.commit_group;" ::: "memory")
#define CP_WAIT1()  asm volatile("cp.async.wait_group 1;" ::: "memory")

__device__ __forceinline__ void cp16(uint32_t d, const void* s) {
    asm volatile("cp.async.cg.shared.global [%0], [%1], 16;" :: "r"(d), "l"(s));
}

// Load ROWS x 64 fp16 K-major tile into SW128 smem with cp.async (256 threads)
template<int ROWS>
__device__ __forceinline__ void cp_tile(uint32_t dbase, const __half* __restrict__ src, int ld) {
#pragma unroll
    for (int it = 0; it < (ROWS * 8) / 256; ++it) {
        int i = threadIdx.x + it * 256;
        int row = i >> 3, c = i & 7;
        uint32_t off = (uint32_t)(row * 128 + c * 16);
        cp16(dbase + swz(off), src + (size_t)row * ld + c * 8);
    }
}

__device__ __forceinline__ void ldsm_x4(uint32_t* r, uint32_t addr) {
    asm volatile("ldmatrix.sync.aligned.m8n8.x4.shared.b16 {%0,%1,%2,%3}, [%4];"
                 : "=r"(r[0]), "=r"(r[1]), "=r"(r[2]), "=r"(r[3]) : "r"(addr));
}

__device__ __forceinline__ void mma_f16(float* c, const uint32_t* a, uint32_t b0, uint32_t b1) {
    asm volatile("mma.sync.aligned.m16n8k16.row.col.f32.f16.f16.f32 "
                 "{%0,%1,%2,%3}, {%4,%5,%6,%7}, {%8,%9}, {%0,%1,%2,%3};"
                 : "+f"(c[0]), "+f"(c[1]), "+f"(c[2]), "+f"(c[3])
                 : "r"(a[0]), "r"(a[1]), "r"(a[2]), "r"(a[3]), "r"(b0), "r"(b1));
}

// ===================== split kernels =====================
__global__ void __launch_bounds__(256) split_x_kernel(const float* __restrict__ x) {
    int idx4 = (blockIdx.x * 256 + threadIdx.x) * 4;
    float4 f = *reinterpret_cast<const float4*>(x + idx4);
    float v[4] = {f.x, f.y, f.z, f.w};
    __half h[4], l[4];
#pragma unroll
    for (int j = 0; j < 4; ++j) {
        h[j] = __float2half(v[j]);
        l[j] = __float2half(v[j] - __half2float(h[j]));
    }
    *reinterpret_cast<uint2*>(g_xh + idx4) = *reinterpret_cast<const uint2*>(h);
    *reinterpret_cast<uint2*>(g_xl + idx4) = *reinterpret_cast<const uint2*>(l);
}

__global__ void __launch_bounds__(256) split_gu_kernel(const float* __restrict__ Wg,
                                                       const float* __restrict__ Wu,
                                                       const int* __restrict__ aidx) {
    int idx4 = (blockIdx.x * 256 + threadIdx.x) * 4;   // < KPAD*HID
    int r = idx4 >> 12;
    int c = idx4 & 4095;
    __half hg[4] = {__half(0.f), __half(0.f), __half(0.f), __half(0.f)};
    __half hu[4] = {__half(0.f), __half(0.f), __half(0.f), __half(0.f)};
    if (r < KACT) {
        int a = aidx[r];
        float4 fg = *reinterpret_cast<const float4*>(Wg + (size_t)a * HID + c);
        float4 fu = *reinterpret_cast<const float4*>(Wu + (size_t)a * HID + c);
        hg[0] = __float2half(fg.x); hg[1] = __float2half(fg.y);
        hg[2] = __float2half(fg.z); hg[3] = __float2half(fg.w);
        hu[0] = __float2half(fu.x); hu[1] = __float2half(fu.y);
        hu[2] = __float2half(fu.z); hu[3] = __float2half(fu.w);
    }
    *reinterpret_cast<uint2*>(g_wg + idx4) = *reinterpret_cast<const uint2*>(hg);
    *reinterpret_cast<uint2*>(g_wu + idx4) = *reinterpret_cast<const uint2*>(hu);
}

__global__ void __launch_bounds__(256) split_wd_kernel(const float* __restrict__ Wd,
                                                       const int* __restrict__ aidx) {
    int idx4 = (blockIdx.x * 256 + threadIdx.x) * 4;   // < HID*KPAD
    int hh = idx4 / KPAD;
    int r  = idx4 - hh * KPAD;
    __half v[4];
#pragma unroll
    for (int j = 0; j < 4; ++j) {
        int k = r + j;
        v[j] = (k < KACT) ? __float2half(Wd[(size_t)hh * WFULL + aidx[k]]) : __half(0.f);
    }
    *reinterpret_cast<uint2*>(g_wd + idx4) = *reinterpret_cast<const uint2*>(v);
}

// ===================== GEMM1: h = silu(x Wg^T) * (x Wu^T) =====================
// CTA tile: M=128, N=64 (both g and u). 8 warps: wm in [0,4) x 32 rows, wn in [0,2) x 32 cols.
// K chunks of 64, 2-stage cp.async pipeline, 2 CTAs/SM.
// Stage layout: xh@0 (16K), xl@16K, wg@32K (8K), wu@40K. Stage = 48K.
#define STG    49152
#define SMEM_REQ (2 * STG + 1024)

__global__ void __launch_bounds__(256, 2) gemm1_kernel() {
    extern __shared__ char smem_raw[];
    char* smem = (char*)(((uintptr_t)smem_raw + 1023) & ~(uintptr_t)1023);
    uint32_t sb = smem_u32(smem);
    const int tid = threadIdx.x, l = tid & 31, wid = tid >> 5;
    const int wm = wid & 3, wn = wid >> 2;
    const int bM = blockIdx.x, bN = blockIdx.y;

    const __half* Ah = g_xh + (size_t)bM * 128 * HID;
    const __half* Al = g_xl + (size_t)bM * 128 * HID;
    const __half* Bg = g_wg + (size_t)bN * 64 * HID;
    const __half* Bu = g_wu + (size_t)bN * 64 * HID;

    float acc_g[2][4][4] = {};
    float acc_u[2][4][4] = {};

    auto load_stage = [&](int ch, int s) {
        uint32_t base = sb + s * STG;
        cp_tile<128>(base +     0, Ah + ch * 64, HID);
        cp_tile<128>(base + 16384, Al + ch * 64, HID);
        cp_tile<64> (base + 32768, Bg + ch * 64, HID);
        cp_tile<64> (base + 40960, Bu + ch * 64, HID);
    };

    load_stage(0, 0); CP_COMMIT();

    for (int ch = 0; ch < NCH1; ++ch) {
        if (ch + 1 < NCH1) load_stage(ch + 1, (ch + 1) & 1);
        CP_COMMIT();
        CP_WAIT1();
        __syncthreads();
        uint32_t base = sb + (ch & 1) * STG;

#pragma unroll
        for (int kk = 0; kk < 4; ++kk) {
            uint32_t ah[2][4], al[2][4];
#pragma unroll
            for (int mi = 0; mi < 2; ++mi) {
                uint32_t off = (uint32_t)((wm * 32 + mi * 16 + (l & 15)) * 128 + (kk * 2 + (l >> 4)) * 16);
                ldsm_x4(ah[mi], base +     0 + swz(off));
                ldsm_x4(al[mi], base + 16384 + swz(off));
            }
            uint32_t bg[2][4], bu[2][4];
#pragma unroll
            for (int ni = 0; ni < 2; ++ni) {
                uint32_t off = (uint32_t)((wn * 32 + ni * 16 + (l & 15)) * 128 + (kk * 2 + (l >> 4)) * 16);
                ldsm_x4(bg[ni], base + 32768 + swz(off));
                ldsm_x4(bu[ni], base + 40960 + swz(off));
            }
#pragma unroll
            for (int mi = 0; mi < 2; ++mi)
#pragma unroll
                for (int ni = 0; ni < 2; ++ni)
#pragma unroll
                    for (int h = 0; h < 2; ++h) {
                        int nj = ni * 2 + h;
                        mma_f16(acc_g[mi][nj], ah[mi], bg[ni][h], bg[ni][2 + h]);
                        mma_f16(acc_g[mi][nj], al[mi], bg[ni][h], bg[ni][2 + h]);
                        mma_f16(acc_u[mi][nj], ah[mi], bu[ni][h], bu[ni][2 + h]);
                        mma_f16(acc_u[mi][nj], al[mi], bu[ni][h], bu[ni][2 + h]);
                    }
        }
        __syncthreads();
    }

    // Epilogue: h = silu(g)*u, fp16 hi/lo split, direct gmem stores.
#pragma unroll
    for (int mi = 0; mi < 2; ++mi)
#pragma unroll
        for (int nj = 0; nj < 4; ++nj) {
            int r = bM * 128 + wm * 32 + mi * 16 + (l >> 2);
            int c = bN * 64 + wn * 32 + nj * 8 + (l & 3) * 2;
#pragma unroll
            for (int half = 0; half < 2; ++half) {
                float g0 = acc_g[mi][nj][half * 2 + 0], g1 = acc_g[mi][nj][half * 2 + 1];
                float u0 = acc_u[mi][nj][half * 2 + 0], u1 = acc_u[mi][nj][half * 2 + 1];
                float h0 = u0 * g0 / (1.f + __expf(-g0));
                float h1 = u1 * g1 / (1.f + __expf(-g1));
                __half h0h = __float2half(h0);
                __half h1h = __float2half(h1);
                __half h0l = __float2half(h0 - __half2float(h0h));
                __half h1l = __float2half(h1 - __half2float(h1h));
                size_t off = (size_t)(r + half * 8) * KPAD + c;
                __half2 ph; ph.x = h0h; ph.y = h1h;
                __half2 pl; pl.x = h0l; pl.y = h1l;
                *reinterpret_cast<__half2*>(g_hh + off) = ph;
                *reinterpret_cast<__half2*>(g_hl + off) = pl;
            }
        }
}

// ===================== GEMM2: out = h Wd^T =====================
// CTA tile: M=128, N=128. 8 warps: wm in [0,4) x 32 rows, wn in [0,2) x 64 cols.
// Stage: hh@0 (16K), hl@16K, wd@32K (16K). Stage = 48K.
__global__ void __launch_bounds__(256, 2) gemm2_kernel(float* __restrict__ out) {
    extern __shared__ char smem_raw[];
    char* smem = (char*)(((uintptr_t)smem_raw + 1023) & ~(uintptr_t)1023);
    uint32_t sb = smem_u32(smem);
    const int tid = threadIdx.x, l = tid & 31, wid = tid >> 5;
    const int wm = wid & 3, wn = wid >> 2;
    const int bM = blockIdx.x, bN = blockIdx.y;

    const __half* Ah = g_hh + (size_t)bM * 128 * KPAD;
    const __half* Al = g_hl + (size_t)bM * 128 * KPAD;
    const __half* Bd = g_wd + (size_t)bN * 128 * KPAD;

    float acc[2][8][4] = {};

    auto load_stage = [&](int ch, int s) {
        uint32_t base = sb + s * STG;
        cp_tile<128>(base +     0, Ah + ch * 64, KPAD);
        cp_tile<128>(base + 16384, Al + ch * 64, KPAD);
        cp_tile<128>(base + 32768, Bd + ch * 64, KPAD);
    };

    load_stage(0, 0); CP_COMMIT();

    for (int ch = 0; ch < NCH2; ++ch) {
        if (ch + 1 < NCH2) load_stage(ch + 1, (ch + 1) & 1);
        CP_COMMIT();
        CP_WAIT1();
        __syncthreads();
        uint32_t base = sb + (ch & 1) * STG;

#pragma unroll
        for (int kk = 0; kk < 4; ++kk) {
            uint32_t ah[2][4], al[2][4];
#pragma unroll
            for (int mi = 0; mi < 2; ++mi) {
                uint32_t off = (uint32_t)((wm * 32 + mi * 16 + (l & 15)) * 128 + (kk * 2 + (l >> 4)) * 16);
                ldsm_x4(ah[mi], base +     0 + swz(off));
                ldsm_x4(al[mi], base + 16384 + swz(off));
            }
            uint32_t bd[4][4];
#pragma unroll
            for (int g4 = 0; g4 < 4; ++g4) {
                uint32_t off = (uint32_t)((wn * 64 + g4 * 16 + (l & 15)) * 128 + (kk * 2 + (l >> 4)) * 16);
                ldsm_x4(bd[g4], base + 32768 + swz(off));
            }
#pragma unroll
            for (int mi = 0; mi < 2; ++mi)
#pragma unroll
                for (int g4 = 0; g4 < 4; ++g4)
#pragma unroll
                    for (int h = 0; h < 2; ++h) {
                        int nj = g4 * 2 + h;
                        mma_f16(acc[mi][nj], ah[mi], bd[g4][h], bd[g4][2 + h]);
                        mma_f16(acc[mi][nj], al[mi], bd[g4][h], bd[g4][2 + h]);
                    }
        }
        __syncthreads();
    }

    // Epilogue: fp32 direct stores (8B per frag-row).
#pragma unroll
    for (int mi = 0; mi < 2; ++mi)
#pragma unroll
        for (int nj = 0; nj < 8; ++nj) {
            int r = bM * 128 + wm * 32 + mi * 16 + (l >> 2);
            int c = bN * 128 + wn * 64 + nj * 8 + (l & 3) * 2;
            float2 v0; v0.x = acc[mi][nj][0]; v0.y = acc[mi][nj][1];
            float2 v1; v1.x = acc[mi][nj][2]; v1.y = acc[mi][nj][3];
            *reinterpret_cast<float2*>(out + (size_t)r * HID + c) = v0;
            *reinterpret_cast<float2*>(out + (size_t)(r + 8) * HID + c) = v1;
        }
}

// ===================== launch =====================
extern "C" void kernel_launch(void* const* d_in, const int* in_sizes, int n_in,
                              void* d_out, int out_size) {
    const float* x  = (const float*)d_in[0];
    const float* Wg = (const float*)d_in[1];
    const float* Wu = (const float*)d_in[2];
    const float* Wd = (const float*)d_in[3];
    const int* aidx = (const int*)d_in[4];
    float* out = (float*)d_out;

    cudaFuncSetAttribute(gemm1_kernel, cudaFuncAttributeMaxDynamicSharedMemorySize, SMEM_REQ);
    cudaFuncSetAttribute(gemm2_kernel, cudaFuncAttributeMaxDynamicSharedMemorySize, SMEM_REQ);

    split_x_kernel<<<(TOK * (size_t)HID) / 1024, 256>>>(x);
    split_gu_kernel<<<((size_t)KPAD * HID) / 1024, 256>>>(Wg, Wu, aidx);
    split_wd_kernel<<<((size_t)HID * KPAD) / 1024, 256>>>(Wd, aidx);
    gemm1_kernel<<<dim3(64, 52), 256, SMEM_REQ>>>();
    gemm2_kernel<<<dim3(64, 32), 256, SMEM_REQ>>>(out);
}

// round 5
// speedup vs baseline: 2.9523x; 1.8799x over previous
#include <cuda_runtime.h>
#include <cuda_fp16.h>
#include <cstdint>

// ===================== problem dims =====================
#define TOK    8192
#define HID    4096
#define KACT   3302
#define KPAD   3328      // 52 * 64
#define WFULL  11008
#define NCH1   64        // 4096 / 64
#define NCH2   52        // 3328 / 64

// ===================== device scratch (static, no allocs) =====================
__device__ __half g_x [(size_t)TOK * HID];
__device__ __half g_wg[(size_t)KPAD * HID];
__device__ __half g_wu[(size_t)KPAD * HID];
__device__ __half g_wd[(size_t)HID * KPAD];
__device__ __half g_h [(size_t)TOK * KPAD];

// ===================== low-level helpers =====================
__device__ __forceinline__ uint32_t smem_u32(const void* p) {
    uint32_t a;
    asm("{ .reg .u64 t; cvta.to.shared.u64 t, %1; cvt.u32.u64 %0, t; }" : "=r"(a) : "l"(p));
    return a;
}
__device__ __forceinline__ uint32_t swz(uint32_t off) {   // SW128: bits[6:4] ^= bits[9:7]
    return off ^ ((off >> 3) & 0x70);
}
#define CP_COMMIT() asm volatile("cp.async.commit_group;" ::: "memory")
#define CP_WAIT2()  asm volatile("cp.async.wait_group 2;" ::: "memory")

__device__ __forceinline__ void cp16(uint32_t d, const void* s) {
    asm volatile("cp.async.cg.shared.global [%0], [%1], 16;" :: "r"(d), "l"(s));
}

// Load ROWS x 64 fp16 K-major tile into SW128 smem with cp.async (256 threads)
template<int ROWS>
__device__ __forceinline__ void cp_tile(uint32_t dbase, const __half* __restrict__ src, int ld) {
#pragma unroll
    for (int it = 0; it < (ROWS * 8) / 256; ++it) {
        int i = threadIdx.x + it * 256;
        int row = i >> 3, c = i & 7;
        uint32_t off = (uint32_t)(row * 128 + c * 16);
        cp16(dbase + swz(off), src + (size_t)row * ld + c * 8);
    }
}

__device__ __forceinline__ void ldsm_x4(uint32_t* r, uint32_t addr) {
    asm volatile("ldmatrix.sync.aligned.m8n8.x4.shared.b16 {%0,%1,%2,%3}, [%4];"
                 : "=r"(r[0]), "=r"(r[1]), "=r"(r[2]), "=r"(r[3]) : "r"(addr));
}

__device__ __forceinline__ void mma_f16(float* c, const uint32_t* a, uint32_t b0, uint32_t b1) {
    asm volatile("mma.sync.aligned.m16n8k16.row.col.f32.f16.f16.f32 "
                 "{%0,%1,%2,%3}, {%4,%5,%6,%7}, {%8,%9}, {%0,%1,%2,%3};"
                 : "+f"(c[0]), "+f"(c[1]), "+f"(c[2]), "+f"(c[3])
                 : "r"(a[0]), "r"(a[1]), "r"(a[2]), "r"(a[3]), "r"(b0), "r"(b1));
}

// ===================== convert kernels =====================
__global__ void __launch_bounds__(256) conv_x_kernel(const float* __restrict__ x) {
    int idx4 = (blockIdx.x * 256 + threadIdx.x) * 4;
    float4 f = *reinterpret_cast<const float4*>(x + idx4);
    __half h[4] = {__float2half(f.x), __float2half(f.y), __float2half(f.z), __float2half(f.w)};
    *reinterpret_cast<uint2*>(g_x + idx4) = *reinterpret_cast<const uint2*>(h);
}

__global__ void __launch_bounds__(256) conv_gu_kernel(const float* __restrict__ Wg,
                                                      const float* __restrict__ Wu,
                                                      const int* __restrict__ aidx) {
    int idx4 = (blockIdx.x * 256 + threadIdx.x) * 4;   // < KPAD*HID
    int r = idx4 >> 12;
    int c = idx4 & 4095;
    __half hg[4] = {__half(0.f), __half(0.f), __half(0.f), __half(0.f)};
    __half hu[4] = {__half(0.f), __half(0.f), __half(0.f), __half(0.f)};
    if (r < KACT) {
        int a = aidx[r];
        float4 fg = *reinterpret_cast<const float4*>(Wg + (size_t)a * HID + c);
        float4 fu = *reinterpret_cast<const float4*>(Wu + (size_t)a * HID + c);
        hg[0] = __float2half(fg.x); hg[1] = __float2half(fg.y);
        hg[2] = __float2half(fg.z); hg[3] = __float2half(fg.w);
        hu[0] = __float2half(fu.x); hu[1] = __float2half(fu.y);
        hu[2] = __float2half(fu.z); hu[3] = __float2half(fu.w);
    }
    *reinterpret_cast<uint2*>(g_wg + idx4) = *reinterpret_cast<const uint2*>(hg);
    *reinterpret_cast<uint2*>(g_wu + idx4) = *reinterpret_cast<const uint2*>(hu);
}

__global__ void __launch_bounds__(256) conv_wd_kernel(const float* __restrict__ Wd,
                                                      const int* __restrict__ aidx) {
    int idx4 = (blockIdx.x * 256 + threadIdx.x) * 4;   // < HID*KPAD
    int hh = idx4 / KPAD;
    int r  = idx4 - hh * KPAD;
    __half v[4];
#pragma unroll
    for (int j = 0; j < 4; ++j) {
        int k = r + j;
        v[j] = (k < KACT) ? __float2half(Wd[(size_t)hh * WFULL + aidx[k]]) : __half(0.f);
    }
    *reinterpret_cast<uint2*>(g_wd + idx4) = *reinterpret_cast<const uint2*>(v);
}

// ===================== GEMM1: h = silu(x Wg^T) * (x Wu^T) =====================
// CTA tile: M=128, N=64 (both g and u). 8 warps: wm in [0,4) x 32 rows, wn in [0,2) x 32 cols.
// K chunks of 64, 3-stage cp.async pipeline, 2 CTAs/SM.
// Stage layout: x@0 (16K), wg@16K (8K), wu@24K (8K). Stage = 32K.
#define STG    32768
#define SMEM_REQ (3 * STG + 1024)

__global__ void __launch_bounds__(256, 2) gemm1_kernel() {
    extern __shared__ char smem_raw[];
    char* smem = (char*)(((uintptr_t)smem_raw + 1023) & ~(uintptr_t)1023);
    uint32_t sb = smem_u32(smem);
    const int tid = threadIdx.x, l = tid & 31, wid = tid >> 5;
    const int wm = wid & 3, wn = wid >> 2;
    const int bM = blockIdx.x, bN = blockIdx.y;

    const __half* Ax = g_x  + (size_t)bM * 128 * HID;
    const __half* Bg = g_wg + (size_t)bN * 64 * HID;
    const __half* Bu = g_wu + (size_t)bN * 64 * HID;

    float acc_g[2][4][4] = {};
    float acc_u[2][4][4] = {};

    auto load_stage = [&](int ch, int s) {
        uint32_t base = sb + s * STG;
        cp_tile<128>(base +     0, Ax + ch * 64, HID);
        cp_tile<64> (base + 16384, Bg + ch * 64, HID);
        cp_tile<64> (base + 24576, Bu + ch * 64, HID);
    };

    load_stage(0, 0); CP_COMMIT();
    load_stage(1, 1); CP_COMMIT();

    for (int ch = 0; ch < NCH1; ++ch) {
        if (ch + 2 < NCH1) load_stage(ch + 2, (ch + 2) % 3);
        CP_COMMIT();
        CP_WAIT2();
        __syncthreads();
        uint32_t base = sb + (ch % 3) * STG;

#pragma unroll
        for (int kk = 0; kk < 4; ++kk) {
            uint32_t ax[2][4];
#pragma unroll
            for (int mi = 0; mi < 2; ++mi) {
                uint32_t off = (uint32_t)((wm * 32 + mi * 16 + (l & 15)) * 128 + (kk * 2 + (l >> 4)) * 16);
                ldsm_x4(ax[mi], base + swz(off));
            }
            uint32_t bg[2][4], bu[2][4];
#pragma unroll
            for (int ni = 0; ni < 2; ++ni) {
                uint32_t off = (uint32_t)((wn * 32 + ni * 16 + (l & 15)) * 128 + (kk * 2 + (l >> 4)) * 16);
                ldsm_x4(bg[ni], base + 16384 + swz(off));
                ldsm_x4(bu[ni], base + 24576 + swz(off));
            }
#pragma unroll
            for (int mi = 0; mi < 2; ++mi)
#pragma unroll
                for (int ni = 0; ni < 2; ++ni)
#pragma unroll
                    for (int h = 0; h < 2; ++h) {
                        int nj = ni * 2 + h;
                        mma_f16(acc_g[mi][nj], ax[mi], bg[ni][h], bg[ni][2 + h]);
                        mma_f16(acc_u[mi][nj], ax[mi], bu[ni][h], bu[ni][2 + h]);
                    }
        }
        __syncthreads();
    }

    // Epilogue: h = silu(g)*u, fp16 store.
#pragma unroll
    for (int mi = 0; mi < 2; ++mi)
#pragma unroll
        for (int nj = 0; nj < 4; ++nj) {
            int r = bM * 128 + wm * 32 + mi * 16 + (l >> 2);
            int c = bN * 64 + wn * 32 + nj * 8 + (l & 3) * 2;
#pragma unroll
            for (int half = 0; half < 2; ++half) {
                float g0 = acc_g[mi][nj][half * 2 + 0], g1 = acc_g[mi][nj][half * 2 + 1];
                float u0 = acc_u[mi][nj][half * 2 + 0], u1 = acc_u[mi][nj][half * 2 + 1];
                float h0 = u0 * g0 / (1.f + __expf(-g0));
                float h1 = u1 * g1 / (1.f + __expf(-g1));
                __half2 ph; ph.x = __float2half(h0); ph.y = __float2half(h1);
                *reinterpret_cast<__half2*>(g_h + (size_t)(r + half * 8) * KPAD + c) = ph;
            }
        }
}

// ===================== GEMM2: out = h Wd^T =====================
// CTA tile: M=128, N=128. 8 warps: wm in [0,4) x 32 rows, wn in [0,2) x 64 cols.
// Stage: h@0 (16K), wd@16K (16K). Stage = 32K, 3 stages.
__global__ void __launch_bounds__(256, 2) gemm2_kernel(float* __restrict__ out) {
    extern __shared__ char smem_raw[];
    char* smem = (char*)(((uintptr_t)smem_raw + 1023) & ~(uintptr_t)1023);
    uint32_t sb = smem_u32(smem);
    const int tid = threadIdx.x, l = tid & 31, wid = tid >> 5;
    const int wm = wid & 3, wn = wid >> 2;
    const int bM = blockIdx.x, bN = blockIdx.y;

    const __half* Ah = g_h  + (size_t)bM * 128 * KPAD;
    const __half* Bd = g_wd + (size_t)bN * 128 * KPAD;

    float acc[2][8][4] = {};

    auto load_stage = [&](int ch, int s) {
        uint32_t base = sb + s * STG;
        cp_tile<128>(base +     0, Ah + ch * 64, KPAD);
        cp_tile<128>(base + 16384, Bd + ch * 64, KPAD);
    };

    load_stage(0, 0); CP_COMMIT();
    load_stage(1, 1); CP_COMMIT();

    for (int ch = 0; ch < NCH2; ++ch) {
        if (ch + 2 < NCH2) load_stage(ch + 2, (ch + 2) % 3);
        CP_COMMIT();
        CP_WAIT2();
        __syncthreads();
        uint32_t base = sb + (ch % 3) * STG;

#pragma unroll
        for (int kk = 0; kk < 4; ++kk) {
            uint32_t ah[2][4];
#pragma unroll
            for (int mi = 0; mi < 2; ++mi) {
                uint32_t off = (uint32_t)((wm * 32 + mi * 16 + (l & 15)) * 128 + (kk * 2 + (l >> 4)) * 16);
                ldsm_x4(ah[mi], base + swz(off));
            }
            uint32_t bd[4][4];
#pragma unroll
            for (int g4 = 0; g4 < 4; ++g4) {
                uint32_t off = (uint32_t)((wn * 64 + g4 * 16 + (l & 15)) * 128 + (kk * 2 + (l >> 4)) * 16);
                ldsm_x4(bd[g4], base + 16384 + swz(off));
            }
#pragma unroll
            for (int mi = 0; mi < 2; ++mi)
#pragma unroll
                for (int g4 = 0; g4 < 4; ++g4)
#pragma unroll
                    for (int h = 0; h < 2; ++h)
                        mma_f16(acc[mi][g4 * 2 + h], ah[mi], bd[g4][h], bd[g4][2 + h]);
        }
        __syncthreads();
    }

    // Epilogue: fp32 direct stores (8B per frag-row).
#pragma unroll
    for (int mi = 0; mi < 2; ++mi)
#pragma unroll
        for (int nj = 0; nj < 8; ++nj) {
            int r = bM * 128 + wm * 32 + mi * 16 + (l >> 2);
            int c = bN * 128 + wn * 64 + nj * 8 + (l & 3) * 2;
            float2 v0; v0.x = acc[mi][nj][0]; v0.y = acc[mi][nj][1];
            float2 v1; v1.x = acc[mi][nj][2]; v1.y = acc[mi][nj][3];
            *reinterpret_cast<float2*>(out + (size_t)r * HID + c) = v0;
            *reinterpret_cast<float2*>(out + (size_t)(r + 8) * HID + c) = v1;
        }
}

// ===================== launch =====================
extern "C" void kernel_launch(void* const* d_in, const int* in_sizes, int n_in,
                              void* d_out, int out_size) {
    const float* x  = (const float*)d_in[0];
    const float* Wg = (const float*)d_in[1];
    const float* Wu = (const float*)d_in[2];
    const float* Wd = (const float*)d_in[3];
    const int* aidx = (const int*)d_in[4];
    float* out = (float*)d_out;

    cudaFuncSetAttribute(gemm1_kernel, cudaFuncAttributeMaxDynamicSharedMemorySize, SMEM_REQ);
    cudaFuncSetAttribute(gemm2_kernel, cudaFuncAttributeMaxDynamicSharedMemorySize, SMEM_REQ);

    conv_x_kernel<<<(TOK * (size_t)HID) / 1024, 256>>>(x);
    conv_gu_kernel<<<((size_t)KPAD * HID) / 1024, 256>>>(Wg, Wu, aidx);
    conv_wd_kernel<<<((size_t)HID * KPAD) / 1024, 256>>>(Wd, aidx);
    gemm1_kernel<<<dim3(64, 52), 256, SMEM_REQ>>>();
    gemm2_kernel<<<dim3(64, 32), 256, SMEM_REQ>>>(out);
}